// round 3
// baseline (speedup 1.0000x reference)
#include <cuda_runtime.h>
#include <math.h>

// Problem shape (fixed by the dataset)
#define BB 16
#define CC 2
#define TT 2000
#define FF 257
#define NCHUNK 40
#define CL 50          // TT / NCHUNK
#define NBLK (BB * NCHUNK)

// Scratch (no cudaMalloc allowed)
__device__ float          g_agg[NBLK * FF];   // chunk-local aggregates
__device__ volatile int   g_flag[NBLK];       // publish flags
__device__ unsigned int   g_vid;              // dynamic block ticket

__global__ void init_kernel() {
    int i = threadIdx.x;
    if (i < NBLK) g_flag[i] = 0;
    if (i == 0) g_vid = 0;
}

__global__ void __launch_bounds__(288, 5)
fused_kernel(const float* __restrict__ in,
             const float* __restrict__ s1,
             const float* __restrict__ weights,
             const float* __restrict__ bias,
             const float* __restrict__ alpha_p,
             float* __restrict__ res,
             float* __restrict__ s_final,
             float* __restrict__ smooth) {
    __shared__ unsigned int s_vid;
    if (threadIdx.x == 0) s_vid = atomicAdd(&g_vid, 1u);
    __syncthreads();
    unsigned int vid = s_vid;
    int b = vid / NCHUNK;
    int chunk = vid % NCHUNK;

    int f = threadIdx.x;
    bool active = (f < FF);
    int fc = active ? f : 0;   // clamped index so inactive lanes stay convergent

    float alpha = 1.0f / (1.0f + expf(-alpha_p[fc]));
    float r = 1.0f - alpha;

    const float2* in0 = (const float2*)in + (size_t)(b * CC + 0) * TT * FF;
    int t0 = chunk * CL;

    // ---------------- Phase 1: chunk-local scan from 0, batched loads ----------------
    float s = 0.0f;
    if (active) {
        const float2* p = in0 + (size_t)t0 * FF + fc;
        for (int tt = 0; tt < CL; tt += 10) {
            float2 x[10];
#pragma unroll
            for (int j = 0; j < 10; ++j) x[j] = p[(size_t)(tt + j) * FF];
#pragma unroll
            for (int j = 0; j < 10; ++j) {
                float d = x[j].x * x[j].x + x[j].y * x[j].y;
                s = fmaf(r, s, alpha * d);
            }
        }
        g_agg[(size_t)vid * FF + fc] = s;
    }
    __syncthreads();
    __threadfence();
    if (threadIdx.x == 0) g_flag[vid] = 1;   // release (fence + volatile store)

    // ---------------- Lookback: fold predecessor aggregates ----------------
    if (threadIdx.x == 0 && chunk > 0) {
        int base = b * NCHUNK;
        for (int c = 0; c < chunk; ++c)
            while (g_flag[base + c] == 0) { }
        __threadfence();                      // acquire
    }
    __syncthreads();

    float rL = 1.0f;
#pragma unroll
    for (int i = 0; i < CL; ++i) rL *= r;     // r^CL

    float prefix = s1[b * FF + fc];
    {
        const float* agg = g_agg + (size_t)(b * NCHUNK) * FF + fc;
        for (int c = 0; c < chunk; ++c)
            prefix = fmaf(rL, prefix, agg[(size_t)c * FF]);
    }

    // ---------------- Phase 3: corrected scan + fused elementwise ----------------
    if (active) {
        float w0 = weights[0 * FF + fc], w1 = weights[1 * FF + fc];
        float b0 = bias[0 * FF + fc],    b1 = bias[1 * FF + fc];

        const float2* in1 = (const float2*)in + (size_t)(b * CC + 1) * TT * FF;
        float2* res0 = (float2*)res + (size_t)(b * CC + 0) * TT * FF;
        float2* res1 = (float2*)res + (size_t)(b * CC + 1) * TT * FF;
        float* sm_out = smooth + (size_t)b * TT * FF;

        float sacc = prefix;
#pragma unroll 5
        for (int t = t0; t < t0 + CL; ++t) {
            size_t idx = (size_t)t * FF + fc;
            float2 x0 = __ldcs(&in0[idx]);    // last use of ch0 (L2 hit from phase 1)
            float2 x1 = __ldcs(&in1[idx]);    // single use of ch1

            float d0 = x0.x * x0.x + x0.y * x0.y;
            sacc = fmaf(r, sacc, alpha * d0);
            float sm = sqrtf(sacc);
            __stcs(&sm_out[idx], sm);

            float inv0 = w0 / (sm + 1e-8f);
            float m1 = sqrtf(x1.x * x1.x + x1.y * x1.y);
            float inv1 = w1 / (m1 + 1e-8f);

            __stcs(&res0[idx], make_float2(fmaf(x0.x, inv0, b0), fmaf(x0.y, inv0, b0)));
            __stcs(&res1[idx], make_float2(fmaf(x1.x, inv1, b1), fmaf(x1.y, inv1, b1)));
        }
        if (chunk == NCHUNK - 1) s_final[b * FF + fc] = sacc;
    }
}

extern "C" void kernel_launch(void* const* d_in, const int* in_sizes, int n_in,
                              void* d_out, int out_size) {
    // metadata order: input, s_1, weights, bias, alpha_param
    const float* in = (const float*)d_in[0];
    const float* s1 = (const float*)d_in[1];
    const float* w  = (const float*)d_in[2];
    const float* bi = (const float*)d_in[3];
    const float* ap = (const float*)d_in[4];

    float* out = (float*)d_out;
    float* res     = out;                                        // [B,C,T,F,2]
    float* s_final = out + (size_t)BB * CC * TT * FF * 2;        // [B,1,F,1]
    float* smooth  = s_final + (size_t)BB * FF;                  // [B,1,T,F,1]

    init_kernel<<<1, NBLK>>>();
    fused_kernel<<<NBLK, 288>>>(in, s1, w, bi, ap, res, s_final, smooth);
}